// round 16
// baseline (speedup 1.0000x reference)
#include <cuda_runtime.h>
#include <math_constants.h>
#include <cstdint>

// ----- problem constants -----
#define B_       16
#define HID_     2048
#define NH_      16
#define NKV_     8
#define HD_      128
#define BLK_     16
#define MAXB_    256
#define QSZ_     2048   // NH*HD
#define KVSZ_    1024   // NKV*HD
#define QKVSZ_   4096
#define NSPLIT_  16
#define CHUNK_   256    // LMAX/NSPLIT
#define TB_      8      // tokens per warp per mainloop iteration
#define SCALE_   0.08838834764831845f  // 128^-0.5
#define EPS_     1e-6f

#define KS_      4      // GEMV K-split (chunks of 512 floats)
#define KCH_     512    // K-chunk size in floats

// ----- scratch -----
__device__ float g_qkvp[KS_][B_ * QKVSZ_];  // qkv partials
__device__ float g_op  [KS_][B_ * HID_];    // o-proj partials
__device__ float g_pmax[B_ * NH_ * NSPLIT_];
__device__ float g_psum[B_ * NH_ * NSPLIT_];
__device__ float g_pacc[B_ * NH_ * NSPLIT_ * HD_];
__device__ float g_attn[B_ * QSZ_];

__device__ __forceinline__ float4 shfl_xor_f4(float4 v, int m) {
    v.x = __shfl_xor_sync(0xffffffffu, v.x, m);
    v.y = __shfl_xor_sync(0xffffffffu, v.y, m);
    v.z = __shfl_xor_sync(0xffffffffu, v.z, m);
    v.w = __shfl_xor_sync(0xffffffffu, v.w, m);
    return v;
}

#define FMA2(acc, a, b) \
    asm volatile("fma.rn.f32x2 %0, %1, %2, %0;" : "+l"(acc) : "l"(a), "l"(b))

// =====================================================================
// GEMV, attention-shaped: y_part[ks][b,o] = x[b,Kchunk] . w[o,Kchunk]
// Block = 256 thr = 8 warps. Stage x chunk (16 batches x 512 floats =
// 32 KB) into smem ONCE (single barrier), then each warp runs with NO
// barriers: burst of 16 independent LDG.128.cs for its 2 out rows'
// weights (full MLP, like the attention mainloop), then pure FFMA2
// against smem x. grid = (out_rows/16, KS_).
// =====================================================================
__global__ void __launch_bounds__(256)
k_gemv_s(const float* __restrict__ x, const float* __restrict__ w,
         float* __restrict__ y, int ostride, int part_stride) {
    __shared__ float sX[B_][KCH_];   // 32 KB
    const int tid = threadIdx.x, lane = tid & 31, wrp = tid >> 5;
    const int ks   = blockIdx.y;
    const int jb   = ks * KCH_;                  // float offset into K
    const int row0 = blockIdx.x * 16 + wrp * 2;  // warp's 2 output rows

    // ---- w burst: 2 rows x 4 float4 = 16 independent LDG.128 (.cs) ----
    unsigned long long wr[2][8];
#pragma unroll
    for (int r = 0; r < 2; r++) {
        const float* wrow = w + (size_t)(row0 + r) * 2048 + jb;
#pragma unroll
        for (int i = 0; i < 4; i++) {
            ulonglong2 v = __ldcs(reinterpret_cast<const ulonglong2*>(
                                      wrow + i * 128 + lane * 4));
            wr[r][2 * i]     = v.x;
            wr[r][2 * i + 1] = v.y;
        }
    }

    // ---- stage x chunk into smem (the only barrier) ----
    for (int i = tid; i < B_ * KCH_ / 4; i += 256) {
        const int b = i >> 7, j = i & 127;       // KCH_/4 = 128 float4
        reinterpret_cast<float4*>(sX[b])[j] =
            __ldg(reinterpret_cast<const float4*>(x + (size_t)b * 2048 + jb) + j);
    }
    __syncthreads();

    // ---- two passes of 8 batches (keeps accumulators at 32 regs) ----
#pragma unroll
    for (int bp = 0; bp < 2; bp++) {
        unsigned long long acc[2][8];
#pragma unroll
        for (int r = 0; r < 2; r++)
#pragma unroll
            for (int b = 0; b < 8; b++) acc[r][b] = 0ull;

#pragma unroll
        for (int b = 0; b < 8; b++) {
            const float* xb = sX[bp * 8 + b];
            unsigned long long xv[8];
#pragma unroll
            for (int i = 0; i < 4; i++) {
                ulonglong2 v = *reinterpret_cast<const ulonglong2*>(
                                   xb + i * 128 + lane * 4);
                xv[2 * i]     = v.x;
                xv[2 * i + 1] = v.y;
            }
#pragma unroll
            for (int p = 0; p < 8; p++) {
                FMA2(acc[0][b], xv[p], wr[0][p]);
                FMA2(acc[1][b], xv[p], wr[1][p]);
            }
        }

        // reduce + store: lane r*8+b stores (batch bp*8+b, row row0+r)
#pragma unroll
        for (int r = 0; r < 2; r++)
#pragma unroll
            for (int b = 0; b < 8; b++) {
                unsigned int lo, hi;
                asm volatile("mov.b64 {%0,%1}, %2;"
                             : "=r"(lo), "=r"(hi) : "l"(acc[r][b]));
                float v = __uint_as_float(lo) + __uint_as_float(hi);
#pragma unroll
                for (int off = 16; off; off >>= 1)
                    v += __shfl_xor_sync(0xffffffffu, v, off);
                if (lane == r * 8 + b)
                    y[(size_t)ks * part_stride +
                      (size_t)(bp * 8 + b) * ostride + row0 + r] = v;
            }
    }
}

// =====================================================================
// Sum the KS_ o-proj partials into the final output.
// =====================================================================
__global__ void __launch_bounds__(128) k_add4(float* __restrict__ out) {
    const int i = blockIdx.x * 128 + threadIdx.x;   // float4 index
    float4 r = make_float4(0.f, 0.f, 0.f, 0.f);
#pragma unroll
    for (int p = 0; p < KS_; p++) {
        const float4 a = reinterpret_cast<const float4*>(g_op[p])[i];
        r.x += a.x;  r.y += a.y;  r.z += a.z;  r.w += a.w;
    }
    reinterpret_cast<float4*>(out)[i] = r;
}

// =====================================================================
// Fused attention: prologue sums the KS_ qkv partials, then RMSNorm +
// RoPE, then split-KV flash decode. grid (NSPLIT, NKV, B), 128 threads.
// =====================================================================
__global__ void __launch_bounds__(128)
k_attn_split(const float* __restrict__ kc,
             const float* __restrict__ vc,
             const int*   __restrict__ btab,
             const int*   __restrict__ ctx_lens,
             const float* __restrict__ qnw,
             const float* __restrict__ knw,
             const float* __restrict__ cs_cache,
             const int*   __restrict__ positions) {
    const int s  = blockIdx.x, kv = blockIdx.y, b = blockIdx.z;
    const int tid = threadIdx.x, lane = tid & 31, wrp = tid >> 5;
    const int ctx   = ctx_lens[b];
    const int start = s * CHUNK_;
    const int end   = min(start + CHUNK_, ctx);

    __shared__ float s_head[4][HD_];   // q0, q1, k_new, v_new

    // ---- prologue ----
    {
        int off;
        const float* nw = nullptr;
        if      (wrp == 0) { off = b * QKVSZ_ + (2 * kv    ) * HD_;        nw = qnw; }
        else if (wrp == 1) { off = b * QKVSZ_ + (2 * kv + 1) * HD_;        nw = qnw; }
        else if (wrp == 2) { off = b * QKVSZ_ + QSZ_ + kv * HD_;           nw = knw; }
        else               { off = b * QKVSZ_ + QSZ_ + KVSZ_ + kv * HD_; }
        float4 x = make_float4(0.f, 0.f, 0.f, 0.f);
#pragma unroll
        for (int p = 0; p < KS_; p++) {
            const float4 t = reinterpret_cast<const float4*>(g_qkvp[p] + off)[lane];
            x.x += t.x;  x.y += t.y;  x.z += t.z;  x.w += t.w;
        }
        if (wrp < 3) {
            float ss = x.x * x.x + x.y * x.y + x.z * x.z + x.w * x.w;
#pragma unroll
            for (int o = 16; o; o >>= 1) ss += __shfl_xor_sync(0xffffffffu, ss, o);
            float rn = rsqrtf(ss * (1.f / HD_) + EPS_);
            const float4 nw4 = reinterpret_cast<const float4*>(nw)[lane];
            x.x *= rn * nw4.x;  x.y *= rn * nw4.y;
            x.z *= rn * nw4.z;  x.w *= rn * nw4.w;
            float4 p = shfl_xor_f4(x, 16);
            const float* cs = cs_cache + (size_t)positions[b] * HD_;
            const int d0 = (lane < 16) ? 4 * lane : 4 * lane - 64;
            const float4 c4 = *reinterpret_cast<const float4*>(cs + d0);
            const float4 s4 = *reinterpret_cast<const float4*>(cs + 64 + d0);
            if (lane < 16) {
                x.x = x.x * c4.x - p.x * s4.x;  x.y = x.y * c4.y - p.y * s4.y;
                x.z = x.z * c4.z - p.z * s4.z;  x.w = x.w * c4.w - p.w * s4.w;
            } else {
                x.x = x.x * c4.x + p.x * s4.x;  x.y = x.y * c4.y + p.y * s4.y;
                x.z = x.z * c4.z + p.z * s4.z;  x.w = x.w * c4.w + p.w * s4.w;
            }
        }
        reinterpret_cast<float4*>(s_head[wrp])[lane] = x;
    }
    __syncthreads();

    const float4 q0 = reinterpret_cast<const float4*>(s_head[0])[lane];
    const float4 q1 = reinterpret_cast<const float4*>(s_head[1])[lane];

    float m0 = -CUDART_INF_F, m1 = -CUDART_INF_F, l0 = 0.f, l1 = 0.f;
    float a0[4] = {0, 0, 0, 0}, a1[4] = {0, 0, 0, 0};
    const int* btr = btab + b * MAXB_;

    for (int base = start + wrp * TB_; base < end; base += 4 * TB_) {
        float4 k4[TB_], v4[TB_];
        float s0[TB_], s1[TB_];
#pragma unroll
        for (int i = 0; i < TB_; i++) {
            int t = base + i;
            if (t < end) {
                if (t == ctx - 1) {
                    k4[i] = reinterpret_cast<const float4*>(s_head[2])[lane];
                    v4[i] = reinterpret_cast<const float4*>(s_head[3])[lane];
                } else {
                    int slot = btr[t >> 4] * BLK_ + (t & (BLK_ - 1));
                    size_t off = ((size_t)slot * NKV_ + kv) * HD_;
                    k4[i] = __ldcs(reinterpret_cast<const float4*>(kc + off) + lane);
                    v4[i] = __ldcs(reinterpret_cast<const float4*>(vc + off) + lane);
                }
            } else {
                k4[i] = make_float4(0.f, 0.f, 0.f, 0.f);
                v4[i] = make_float4(0.f, 0.f, 0.f, 0.f);
            }
        }
#pragma unroll
        for (int i = 0; i < TB_; i++) {
            s0[i] = q0.x * k4[i].x + q0.y * k4[i].y + q0.z * k4[i].z + q0.w * k4[i].w;
            s1[i] = q1.x * k4[i].x + q1.y * k4[i].y + q1.z * k4[i].z + q1.w * k4[i].w;
        }
#pragma unroll
        for (int off = 16; off; off >>= 1) {
#pragma unroll
            for (int i = 0; i < TB_; i++) {
                s0[i] += __shfl_xor_sync(0xffffffffu, s0[i], off);
                s1[i] += __shfl_xor_sync(0xffffffffu, s1[i], off);
            }
        }
        float bm0 = -CUDART_INF_F, bm1 = -CUDART_INF_F;
#pragma unroll
        for (int i = 0; i < TB_; i++) {
            if (base + i < end) { s0[i] *= SCALE_; s1[i] *= SCALE_; }
            else                { s0[i] = -CUDART_INF_F; s1[i] = -CUDART_INF_F; }
            bm0 = fmaxf(bm0, s0[i]);
            bm1 = fmaxf(bm1, s1[i]);
        }
        float nm0 = fmaxf(m0, bm0), nm1 = fmaxf(m1, bm1);
        float f0 = __expf(m0 - nm0), f1 = __expf(m1 - nm1);
        l0 *= f0;  l1 *= f1;
#pragma unroll
        for (int j = 0; j < 4; j++) { a0[j] *= f0; a1[j] *= f1; }
#pragma unroll
        for (int i = 0; i < TB_; i++) {
            float p0 = __expf(s0[i] - nm0);
            float p1 = __expf(s1[i] - nm1);
            l0 += p0;  l1 += p1;
            a0[0] += p0 * v4[i].x;  a1[0] += p1 * v4[i].x;
            a0[1] += p0 * v4[i].y;  a1[1] += p1 * v4[i].y;
            a0[2] += p0 * v4[i].z;  a1[2] += p1 * v4[i].z;
            a0[3] += p0 * v4[i].w;  a1[3] += p1 * v4[i].w;
        }
        m0 = nm0;  m1 = nm1;
    }

    // combine the 4 warps
    __shared__ float sm[2][4], sl[2][4], sa[2][4][HD_];
    if (lane == 0) { sm[0][wrp] = m0; sm[1][wrp] = m1; sl[0][wrp] = l0; sl[1][wrp] = l1; }
#pragma unroll
    for (int j = 0; j < 4; j++) {
        sa[0][wrp][lane * 4 + j] = a0[j];
        sa[1][wrp][lane * 4 + j] = a1[j];
    }
    __syncthreads();
#pragma unroll
    for (int h = 0; h < 2; h++) {
        float M = fmaxf(fmaxf(sm[h][0], sm[h][1]), fmaxf(sm[h][2], sm[h][3]));
        float L = 0.f, A = 0.f;
#pragma unroll
        for (int wv = 0; wv < 4; wv++) {
            float mw = sm[h][wv];
            float f  = (mw == -CUDART_INF_F) ? 0.f : __expf(mw - M);
            L += sl[h][wv] * f;
            A += sa[h][wv][tid] * f;
        }
        int idx = ((b * NH_ + kv * 2 + h) * NSPLIT_ + s);
        g_pacc[(size_t)idx * HD_ + tid] = A;
        if (tid == 0) { g_pmax[idx] = M; g_psum[idx] = L; }
    }
}

// =====================================================================
// Combine splits: one warp per (b, qhead). grid 64 x 128 threads.
// =====================================================================
__global__ void __launch_bounds__(128) k_attn_combine() {
    const int bq   = blockIdx.x * 4 + (threadIdx.x >> 5);
    const int lane = threadIdx.x & 31;
    float mv = (lane < NSPLIT_) ? g_pmax[bq * NSPLIT_ + lane] : -CUDART_INF_F;
    float M = mv;
#pragma unroll
    for (int off = 16; off; off >>= 1) M = fmaxf(M, __shfl_xor_sync(0xffffffffu, M, off));
    float f  = (lane < NSPLIT_ && mv != -CUDART_INF_F) ? __expf(mv - M) : 0.f;
    float lv = (lane < NSPLIT_) ? g_psum[bq * NSPLIT_ + lane] : 0.f;
    float L = lv * f;
#pragma unroll
    for (int off = 16; off; off >>= 1) L += __shfl_xor_sync(0xffffffffu, L, off);
    float4 A = make_float4(0.f, 0.f, 0.f, 0.f);
#pragma unroll
    for (int s = 0; s < NSPLIT_; s++) {
        float fs = __shfl_sync(0xffffffffu, f, s);
        if (fs != 0.f) {
            float4 p = reinterpret_cast<const float4*>(
                           g_pacc + ((size_t)bq * NSPLIT_ + s) * HD_)[lane];
            A.x += fs * p.x;  A.y += fs * p.y;  A.z += fs * p.z;  A.w += fs * p.w;
        }
    }
    const float inv = 1.f / L;
    A.x *= inv;  A.y *= inv;  A.z *= inv;  A.w *= inv;
    reinterpret_cast<float4*>(g_attn + bq * HD_)[lane] = A;
}

// =====================================================================
extern "C" void kernel_launch(void* const* d_in, const int* in_sizes, int n_in,
                              void* d_out, int out_size) {
    const float* hidden   = (const float*)d_in[0];
    const int*   positions= (const int*)  d_in[1];
    const float* qkv_w    = (const float*)d_in[2];
    const float* q_norm_w = (const float*)d_in[3];
    const float* k_norm_w = (const float*)d_in[4];
    const float* o_w      = (const float*)d_in[5];
    const float* cs_cache = (const float*)d_in[6];
    const float* k_cache  = (const float*)d_in[7];
    const float* v_cache  = (const float*)d_in[8];
    // d_in[9] = slot_mapping (derived internally, unused)
    const int*   btab     = (const int*)  d_in[10];
    const int*   ctx_lens = (const int*)  d_in[11];
    float* out = (float*)d_out;

    float* d_qkvp; cudaGetSymbolAddress((void**)&d_qkvp, g_qkvp);
    float* d_op;   cudaGetSymbolAddress((void**)&d_op,   g_op);
    float* d_attn; cudaGetSymbolAddress((void**)&d_attn, g_attn);

    // qkv: (256, 4) = 1024 blocks x 256 thr
    k_gemv_s<<<dim3(QKVSZ_ / 16, KS_), 256>>>(hidden, qkv_w, d_qkvp,
                                              QKVSZ_, B_ * QKVSZ_);
    k_attn_split<<<dim3(NSPLIT_, NKV_, B_), 128>>>(k_cache, v_cache, btab, ctx_lens,
                                                   q_norm_w, k_norm_w, cs_cache, positions);
    k_attn_combine<<<B_ * NH_ / 4, 128>>>();
    // oproj: (128, 4) = 512 blocks x 256 thr
    k_gemv_s<<<dim3(HID_ / 16, KS_), 256>>>(d_attn, o_w, d_op,
                                            HID_, B_ * HID_);
    k_add4<<<(B_ * HID_ / 4) / 128, 128>>>(out);
}

// round 17
// speedup vs baseline: 1.2980x; 1.2980x over previous
#include <cuda_runtime.h>
#include <math_constants.h>
#include <cstdint>

// ----- problem constants -----
#define B_       16
#define HID_     2048
#define NH_      16
#define NKV_     8
#define HD_      128
#define BLK_     16
#define MAXB_    256
#define QSZ_     2048   // NH*HD
#define KVSZ_    1024   // NKV*HD
#define QKVSZ_   4096
#define NSPLIT_  16
#define CHUNK_   256    // LMAX/NSPLIT
#define TB_      8      // tokens per warp per mainloop iteration
#define SCALE_   0.08838834764831845f  // 128^-0.5
#define EPS_     1e-6f

// GEMV pipeline config
#define GS_      6      // cp.async stages (deeper in-flight: 5 chunks)
#define NCH_     16     // K chunks (2048 / 128)

// ----- scratch -----
__device__ float g_qkv [B_ * QKVSZ_];
__device__ float g_pmax[B_ * NH_ * NSPLIT_];
__device__ float g_psum[B_ * NH_ * NSPLIT_];
__device__ float g_pacc[B_ * NH_ * NSPLIT_ * HD_];
__device__ float g_attn[B_ * QSZ_];

__device__ __forceinline__ float4 shfl_xor_f4(float4 v, int m) {
    v.x = __shfl_xor_sync(0xffffffffu, v.x, m);
    v.y = __shfl_xor_sync(0xffffffffu, v.y, m);
    v.z = __shfl_xor_sync(0xffffffffu, v.z, m);
    v.w = __shfl_xor_sync(0xffffffffu, v.w, m);
    return v;
}

#define FMA2(acc, a, b) \
    asm volatile("fma.rn.f32x2 %0, %1, %2, %0;" : "+l"(acc) : "l"(a), "l"(b))

// =====================================================================
// GEMV (K = 2048): y[b, o] = x[b,:] . w[o,:]
// 128 threads = 4 warps. Block owns 8 output rows; warp owns 4 batch
// rows x 8 out rows. Weights streamed via 6-stage cp.async pipeline
// (5 chunks = 20 KB in flight per block); x read from L2 with register
// prefetch. Accumulation in packed f32x2 (FFMA2, 2x fp32 rate).
// =====================================================================
__global__ void __launch_bounds__(128)
k_gemv2(const float* __restrict__ x, const float* __restrict__ w,
        float* __restrict__ y, int ostride) {
    __shared__ float4 sW[GS_][8][32];   // 24 KB
    const int tid = threadIdx.x, lane = tid & 31, wrp = tid >> 5;
    const int o0 = blockIdx.x * 8;
    const int b0 = wrp * 4;
    const float4* wp = reinterpret_cast<const float4*>(w) + (size_t)o0 * 512;
    const float4* xp = reinterpret_cast<const float4*>(x);

    // ---- async copy of one 8x32-float4 weight chunk into stage ----
    auto issue = [&](int stage, int c) {
#pragma unroll
        for (int i = 0; i < 2; i++) {
            const int idx = tid + i * 128;         // 0..255
            const int r = idx >> 5, cc = idx & 31;
            unsigned int dst = (unsigned int)__cvta_generic_to_shared(&sW[stage][r][cc]);
            const float4* src = wp + (size_t)r * 512 + c * 32 + cc;
            asm volatile("cp.async.cg.shared.global [%0], [%1], 16;"
                         :: "r"(dst), "l"(src));
        }
        asm volatile("cp.async.commit_group;");
    };

    // prologue: stages 0..GS-2 (chunks 0..4 in flight)
#pragma unroll
    for (int s = 0; s < GS_ - 1; s++) issue(s, s);

    // x prefetch (chunk 0) as packed u64 pairs
    unsigned long long xr[4][2];
#pragma unroll
    for (int bb = 0; bb < 4; bb++) {
        const float4* p = xp + (size_t)(b0 + bb) * 512 + lane;
        asm volatile("ld.global.nc.v2.u64 {%0,%1}, [%2];"
                     : "=l"(xr[bb][0]), "=l"(xr[bb][1]) : "l"(p));
    }

    unsigned long long acc[4][8];
#pragma unroll
    for (int bb = 0; bb < 4; bb++)
#pragma unroll
        for (int r = 0; r < 8; r++) acc[bb][r] = 0ull;

    const unsigned int wbase = (unsigned int)__cvta_generic_to_shared(&sW[0][0][lane]);

    for (int c = 0; c < NCH_; c++) {
        asm volatile("cp.async.wait_group %0;" :: "n"(GS_ - 2));
        __syncthreads();
        const int cn = c + GS_ - 1;
        if (cn < NCH_) issue(cn % GS_, cn);
        else asm volatile("cp.async.commit_group;");

        // grab current x, prefetch next chunk
        unsigned long long cur[4][2];
#pragma unroll
        for (int bb = 0; bb < 4; bb++) { cur[bb][0] = xr[bb][0]; cur[bb][1] = xr[bb][1]; }
        if (c + 1 < NCH_) {
#pragma unroll
            for (int bb = 0; bb < 4; bb++) {
                const float4* p = xp + (size_t)(b0 + bb) * 512 + (c + 1) * 32 + lane;
                asm volatile("ld.global.nc.v2.u64 {%0,%1}, [%2];"
                             : "=l"(xr[bb][0]), "=l"(xr[bb][1]) : "l"(p));
            }
        }

        const unsigned int stb = wbase + (c % GS_) * 8 * 512;  // stage base (bytes)
#pragma unroll
        for (int r = 0; r < 8; r++) {
            unsigned long long w0, w1;
            asm volatile("ld.shared.v2.u64 {%0,%1}, [%2];"
                         : "=l"(w0), "=l"(w1) : "r"(stb + r * 512));
#pragma unroll
            for (int bb = 0; bb < 4; bb++) {
                FMA2(acc[bb][r], cur[bb][0], w0);
                FMA2(acc[bb][r], cur[bb][1], w1);
            }
        }
    }

    // epilogue: unpack f32x2, warp-reduce, store
#pragma unroll
    for (int bb = 0; bb < 4; bb++)
#pragma unroll
        for (int r = 0; r < 8; r++) {
            unsigned int lo, hi;
            asm volatile("mov.b64 {%0,%1}, %2;" : "=r"(lo), "=r"(hi) : "l"(acc[bb][r]));
            float v = __uint_as_float(lo) + __uint_as_float(hi);
#pragma unroll
            for (int off = 16; off; off >>= 1) v += __shfl_xor_sync(0xffffffffu, v, off);
            if (lane == bb * 8 + r)
                y[(size_t)(b0 + bb) * ostride + o0 + r] = v;
        }
}

// =====================================================================
// Fused attention: per-block norm+RoPE prologue + split-KV flash decode.
// grid (NSPLIT, NKV, B), 128 threads (4 warps).
// =====================================================================
__global__ void __launch_bounds__(128)
k_attn_split(const float* __restrict__ kc,
             const float* __restrict__ vc,
             const int*   __restrict__ btab,
             const int*   __restrict__ ctx_lens,
             const float* __restrict__ qnw,
             const float* __restrict__ knw,
             const float* __restrict__ cs_cache,
             const int*   __restrict__ positions) {
    const int s  = blockIdx.x, kv = blockIdx.y, b = blockIdx.z;
    const int tid = threadIdx.x, lane = tid & 31, wrp = tid >> 5;
    const int ctx   = ctx_lens[b];
    const int start = s * CHUNK_;
    const int end   = min(start + CHUNK_, ctx);

    __shared__ float s_head[4][HD_];   // q0, q1, k_new, v_new

    // ---- prologue: RMSNorm + RoPE for this block's heads ----
    {
        const float* base = g_qkv + b * QKVSZ_;
        const float* src;
        const float* nw = nullptr;
        if      (wrp == 0) { src = base + (2 * kv    ) * HD_;          nw = qnw; }
        else if (wrp == 1) { src = base + (2 * kv + 1) * HD_;          nw = qnw; }
        else if (wrp == 2) { src = base + QSZ_ + kv * HD_;             nw = knw; }
        else               { src = base + QSZ_ + KVSZ_ + kv * HD_; }
        float4 x = reinterpret_cast<const float4*>(src)[lane];
        if (wrp < 3) {
            float ss = x.x * x.x + x.y * x.y + x.z * x.z + x.w * x.w;
#pragma unroll
            for (int o = 16; o; o >>= 1) ss += __shfl_xor_sync(0xffffffffu, ss, o);
            float rn = rsqrtf(ss * (1.f / HD_) + EPS_);
            const float4 nw4 = reinterpret_cast<const float4*>(nw)[lane];
            x.x *= rn * nw4.x;  x.y *= rn * nw4.y;
            x.z *= rn * nw4.z;  x.w *= rn * nw4.w;
            float4 p = shfl_xor_f4(x, 16);
            const float* cs = cs_cache + (size_t)positions[b] * HD_;
            const int d0 = (lane < 16) ? 4 * lane : 4 * lane - 64;
            const float4 c4 = *reinterpret_cast<const float4*>(cs + d0);
            const float4 s4 = *reinterpret_cast<const float4*>(cs + 64 + d0);
            if (lane < 16) {
                x.x = x.x * c4.x - p.x * s4.x;  x.y = x.y * c4.y - p.y * s4.y;
                x.z = x.z * c4.z - p.z * s4.z;  x.w = x.w * c4.w - p.w * s4.w;
            } else {
                x.x = x.x * c4.x + p.x * s4.x;  x.y = x.y * c4.y + p.y * s4.y;
                x.z = x.z * c4.z + p.z * s4.z;  x.w = x.w * c4.w + p.w * s4.w;
            }
        }
        reinterpret_cast<float4*>(s_head[wrp])[lane] = x;
    }
    __syncthreads();

    const float4 q0 = reinterpret_cast<const float4*>(s_head[0])[lane];
    const float4 q1 = reinterpret_cast<const float4*>(s_head[1])[lane];

    float m0 = -CUDART_INF_F, m1 = -CUDART_INF_F, l0 = 0.f, l1 = 0.f;
    float a0[4] = {0, 0, 0, 0}, a1[4] = {0, 0, 0, 0};
    const int* btr = btab + b * MAXB_;

    for (int base = start + wrp * TB_; base < end; base += 4 * TB_) {
        float4 k4[TB_], v4[TB_];
        float s0[TB_], s1[TB_];
#pragma unroll
        for (int i = 0; i < TB_; i++) {
            int t = base + i;
            if (t < end) {
                if (t == ctx - 1) {
                    k4[i] = reinterpret_cast<const float4*>(s_head[2])[lane];
                    v4[i] = reinterpret_cast<const float4*>(s_head[3])[lane];
                } else {
                    int slot = btr[t >> 4] * BLK_ + (t & (BLK_ - 1));
                    size_t off = ((size_t)slot * NKV_ + kv) * HD_;
                    k4[i] = __ldcs(reinterpret_cast<const float4*>(kc + off) + lane);
                    v4[i] = __ldcs(reinterpret_cast<const float4*>(vc + off) + lane);
                }
            } else {
                k4[i] = make_float4(0.f, 0.f, 0.f, 0.f);
                v4[i] = make_float4(0.f, 0.f, 0.f, 0.f);
            }
        }
#pragma unroll
        for (int i = 0; i < TB_; i++) {
            s0[i] = q0.x * k4[i].x + q0.y * k4[i].y + q0.z * k4[i].z + q0.w * k4[i].w;
            s1[i] = q1.x * k4[i].x + q1.y * k4[i].y + q1.z * k4[i].z + q1.w * k4[i].w;
        }
#pragma unroll
        for (int off = 16; off; off >>= 1) {
#pragma unroll
            for (int i = 0; i < TB_; i++) {
                s0[i] += __shfl_xor_sync(0xffffffffu, s0[i], off);
                s1[i] += __shfl_xor_sync(0xffffffffu, s1[i], off);
            }
        }
        float bm0 = -CUDART_INF_F, bm1 = -CUDART_INF_F;
#pragma unroll
        for (int i = 0; i < TB_; i++) {
            if (base + i < end) { s0[i] *= SCALE_; s1[i] *= SCALE_; }
            else                { s0[i] = -CUDART_INF_F; s1[i] = -CUDART_INF_F; }
            bm0 = fmaxf(bm0, s0[i]);
            bm1 = fmaxf(bm1, s1[i]);
        }
        float nm0 = fmaxf(m0, bm0), nm1 = fmaxf(m1, bm1);
        float f0 = __expf(m0 - nm0), f1 = __expf(m1 - nm1);
        l0 *= f0;  l1 *= f1;
#pragma unroll
        for (int j = 0; j < 4; j++) { a0[j] *= f0; a1[j] *= f1; }
#pragma unroll
        for (int i = 0; i < TB_; i++) {
            float p0 = __expf(s0[i] - nm0);
            float p1 = __expf(s1[i] - nm1);
            l0 += p0;  l1 += p1;
            a0[0] += p0 * v4[i].x;  a1[0] += p1 * v4[i].x;
            a0[1] += p0 * v4[i].y;  a1[1] += p1 * v4[i].y;
            a0[2] += p0 * v4[i].z;  a1[2] += p1 * v4[i].z;
            a0[3] += p0 * v4[i].w;  a1[3] += p1 * v4[i].w;
        }
        m0 = nm0;  m1 = nm1;
    }

    // combine the 4 warps
    __shared__ float sm[2][4], sl[2][4], sa[2][4][HD_];
    if (lane == 0) { sm[0][wrp] = m0; sm[1][wrp] = m1; sl[0][wrp] = l0; sl[1][wrp] = l1; }
#pragma unroll
    for (int j = 0; j < 4; j++) {
        sa[0][wrp][lane * 4 + j] = a0[j];
        sa[1][wrp][lane * 4 + j] = a1[j];
    }
    __syncthreads();
#pragma unroll
    for (int h = 0; h < 2; h++) {
        float M = fmaxf(fmaxf(sm[h][0], sm[h][1]), fmaxf(sm[h][2], sm[h][3]));
        float L = 0.f, A = 0.f;
#pragma unroll
        for (int wv = 0; wv < 4; wv++) {
            float mw = sm[h][wv];
            float f  = (mw == -CUDART_INF_F) ? 0.f : __expf(mw - M);
            L += sl[h][wv] * f;
            A += sa[h][wv][tid] * f;
        }
        int idx = ((b * NH_ + kv * 2 + h) * NSPLIT_ + s);
        g_pacc[(size_t)idx * HD_ + tid] = A;
        if (tid == 0) { g_pmax[idx] = M; g_psum[idx] = L; }
    }
}

// =====================================================================
// Combine splits: one warp per (b, qhead). grid 64 x 128 threads.
// =====================================================================
__global__ void __launch_bounds__(128) k_attn_combine() {
    const int bq   = blockIdx.x * 4 + (threadIdx.x >> 5);
    const int lane = threadIdx.x & 31;
    float mv = (lane < NSPLIT_) ? g_pmax[bq * NSPLIT_ + lane] : -CUDART_INF_F;
    float M = mv;
#pragma unroll
    for (int off = 16; off; off >>= 1) M = fmaxf(M, __shfl_xor_sync(0xffffffffu, M, off));
    float f  = (lane < NSPLIT_ && mv != -CUDART_INF_F) ? __expf(mv - M) : 0.f;
    float lv = (lane < NSPLIT_) ? g_psum[bq * NSPLIT_ + lane] : 0.f;
    float L = lv * f;
#pragma unroll
    for (int off = 16; off; off >>= 1) L += __shfl_xor_sync(0xffffffffu, L, off);
    float4 A = make_float4(0.f, 0.f, 0.f, 0.f);
#pragma unroll
    for (int s = 0; s < NSPLIT_; s++) {
        float fs = __shfl_sync(0xffffffffu, f, s);
        if (fs != 0.f) {
            float4 p = reinterpret_cast<const float4*>(
                           g_pacc + ((size_t)bq * NSPLIT_ + s) * HD_)[lane];
            A.x += fs * p.x;  A.y += fs * p.y;  A.z += fs * p.z;  A.w += fs * p.w;
        }
    }
    const float inv = 1.f / L;
    A.x *= inv;  A.y *= inv;  A.z *= inv;  A.w *= inv;
    reinterpret_cast<float4*>(g_attn + bq * HD_)[lane] = A;
}

// =====================================================================
extern "C" void kernel_launch(void* const* d_in, const int* in_sizes, int n_in,
                              void* d_out, int out_size) {
    const float* hidden   = (const float*)d_in[0];
    const int*   positions= (const int*)  d_in[1];
    const float* qkv_w    = (const float*)d_in[2];
    const float* q_norm_w = (const float*)d_in[3];
    const float* k_norm_w = (const float*)d_in[4];
    const float* o_w      = (const float*)d_in[5];
    const float* cs_cache = (const float*)d_in[6];
    const float* k_cache  = (const float*)d_in[7];
    const float* v_cache  = (const float*)d_in[8];
    // d_in[9] = slot_mapping (derived internally, unused)
    const int*   btab     = (const int*)  d_in[10];
    const int*   ctx_lens = (const int*)  d_in[11];
    float* out = (float*)d_out;

    float* d_qkv;  cudaGetSymbolAddress((void**)&d_qkv,  g_qkv);
    float* d_attn; cudaGetSymbolAddress((void**)&d_attn, g_attn);

    k_gemv2<<<QKVSZ_ / 8, 128>>>(hidden, qkv_w, d_qkv, QKVSZ_);
    k_attn_split<<<dim3(NSPLIT_, NKV_, B_), 128>>>(k_cache, v_cache, btab, ctx_lens,
                                                   q_norm_w, k_norm_w, cs_cache, positions);
    k_attn_combine<<<B_ * NH_ / 4, 128>>>();
    k_gemv2<<<HID_ / 8, 128>>>(d_attn, o_w, out, HID_);
}